// round 6
// baseline (speedup 1.0000x reference)
#include <cuda_runtime.h>

#define N_NODES 50000
#define N_EDGES 800000
#define F 96

// Scratch (device globals; no allocation allowed)
__device__ int   g_deg[N_NODES];
__device__ int   g_off[N_NODES + 1];
__device__ int   g_cur[N_NODES];
__device__ int   g_srcs[N_EDGES];
__device__ float g_agg[N_NODES * F];
__device__ float g_h[N_NODES * F];

__global__ void k_zero(int n) {
    int i = blockIdx.x * blockDim.x + threadIdx.x;
    if (i < n) g_deg[i] = 0;
}

__global__ void k_hist(const int* __restrict__ ei, int E) {
    int e = blockIdx.x * blockDim.x + threadIdx.x;
    if (e < E) {
        int dst = ei[E + e];
        if ((unsigned)dst < N_NODES) atomicAdd(&g_deg[dst], 1);
    }
}

// Single-block exclusive scan of g_deg -> g_off (and g_cur copy)
__global__ void k_scan(int n, int E) {
    __shared__ int sh[1024];
    int t = threadIdx.x;
    int C = (n + 1023) / 1024;          // 49
    int base = t * C;
    int end = min(base + C, n);
    int s = 0;
    for (int i = base; i < end; i++) s += g_deg[i];
    sh[t] = s;
    __syncthreads();
    for (int d = 1; d < 1024; d <<= 1) {
        int v = (t >= d) ? sh[t - d] : 0;
        __syncthreads();
        if (t >= d) sh[t] += v;
        __syncthreads();
    }
    int run = (t == 0) ? 0 : sh[t - 1];
    for (int i = base; i < end; i++) {
        g_off[i] = run;
        g_cur[i] = run;
        run += g_deg[i];
    }
    if (t == 0) g_off[n] = E;
}

__global__ void k_scatter(const int* __restrict__ ei, int E) {
    int e = blockIdx.x * blockDim.x + threadIdx.x;
    if (e < E) {
        int src = ei[e];
        int dst = ei[E + e];
        if ((unsigned)dst < N_NODES && (unsigned)src < N_NODES) {
            int p = atomicAdd(&g_cur[dst], 1);
            if ((unsigned)p < N_EDGES) g_srcs[p] = src;
        }
    }
}

// Segment-mean aggregation: block = (96, 4), 4 nodes per block.
// Thread f accumulates feature f over this node's neighbor list.
__global__ void k_agg(const float* __restrict__ in, float* __restrict__ out, int n) {
    int node = blockIdx.x * blockDim.y + threadIdx.y;
    int f = threadIdx.x;
    if (node >= n) return;
    int o0 = g_off[node];
    int o1 = g_off[node + 1];
    float s = 0.f;
    for (int j = o0; j < o1; j++) {
        int src = __ldg(&g_srcs[j]);
        s += __ldg(&in[src * F + f]);
    }
    int d = o1 - o0;
    out[node * F + f] = (d > 0) ? s * (1.0f / (float)d) : 0.0f;
}

// Fused GEMM: out[i][n] = act( sum_k Wl[n][k]*A[i][k] + sum_k Wr[n][k]*X[i][k] + b[n] )
// 256 threads = 16(ty over M) x 16(tx over N). BM=64 (TM=4), BN=NOUT (TN=NOUT/16), BK=8.
template <int NOUT, int TN, bool RELU>
__global__ void k_gemm(const float* __restrict__ A, const float* __restrict__ X,
                       const float* __restrict__ Wl, const float* __restrict__ Wr,
                       const float* __restrict__ bias, float* __restrict__ out, int M) {
    const int BM = 64, BK = 8, TM = 4;
    __shared__ float As[BK][BM + 4];
    __shared__ float Ws[BK][NOUT];

    int tid = threadIdx.x;
    int tx = tid & 15;
    int ty = tid >> 4;
    int rowBase = blockIdx.x * BM;

    float acc[TM][TN];
#pragma unroll
    for (int m = 0; m < TM; m++)
#pragma unroll
        for (int n = 0; n < TN; n++) acc[m][n] = bias[tx * TN + n];

#pragma unroll
    for (int pass = 0; pass < 2; pass++) {
        const float* src = pass ? X : A;
        const float* W = pass ? Wr : Wl;
        for (int k0 = 0; k0 < F; k0 += BK) {
            // A tile: 64 rows x 8 k = 512 elems, 2 per thread
#pragma unroll
            for (int l = 0; l < 2; l++) {
                int idx = tid + l * 256;
                int r = idx >> 3;
                int kk = idx & 7;
                int row = rowBase + r;
                As[kk][r] = (row < M) ? src[row * F + k0 + kk] : 0.f;
            }
            // W tile: NOUT x 8
            for (int idx = tid; idx < NOUT * BK; idx += 256) {
                int n = idx >> 3;
                int kk = idx & 7;
                Ws[kk][n] = W[n * F + k0 + kk];
            }
            __syncthreads();
#pragma unroll
            for (int kk = 0; kk < BK; kk++) {
                float a[TM], w[TN];
#pragma unroll
                for (int m = 0; m < TM; m++) a[m] = As[kk][ty * TM + m];
#pragma unroll
                for (int n = 0; n < TN; n++) w[n] = Ws[kk][tx * TN + n];
#pragma unroll
                for (int m = 0; m < TM; m++)
#pragma unroll
                    for (int n = 0; n < TN; n++) acc[m][n] += a[m] * w[n];
            }
            __syncthreads();
        }
    }

#pragma unroll
    for (int m = 0; m < TM; m++) {
        int row = rowBase + ty * TM + m;
        if (row < M) {
#pragma unroll
            for (int n = 0; n < TN; n++) {
                float v = acc[m][n];
                if (RELU) v = fmaxf(v, 0.f);
                out[row * NOUT + tx * TN + n] = v;
            }
        }
    }
}

extern "C" void kernel_launch(void* const* d_in, const int* in_sizes, int n_in,
                              void* d_out, int out_size) {
    const float* x   = (const float*)d_in[0];
    const int*   ei  = (const int*)d_in[1];     // int32 edge_index [2, E]
    const float* w1l = (const float*)d_in[2];
    const float* b1  = (const float*)d_in[3];
    const float* w1r = (const float*)d_in[4];
    const float* w2l = (const float*)d_in[5];
    const float* b2  = (const float*)d_in[6];
    const float* w2r = (const float*)d_in[7];
    float* out = (float*)d_out;

    const int N = N_NODES;
    const int E = in_sizes[1] / 2;   // element count of edge_index = 2*E

    void* p_agg = nullptr;
    void* p_h = nullptr;
    cudaGetSymbolAddress(&p_agg, g_agg);
    cudaGetSymbolAddress(&p_h, g_h);
    float* agg = (float*)p_agg;
    float* h   = (float*)p_h;

    // CSR build
    k_zero<<<(N + 255) / 256, 256>>>(N);
    k_hist<<<(E + 255) / 256, 256>>>(ei, E);
    k_scan<<<1, 1024>>>(N, E);
    k_scatter<<<(E + 255) / 256, 256>>>(ei, E);

    dim3 ab(96, 4);
    int agrid = (N + 3) / 4;

    // Layer 1
    k_agg<<<agrid, ab>>>(x, agg, N);
    k_gemm<96, 6, true><<<(N + 63) / 64, 256>>>(agg, x, w1l, w1r, b1, h, N);

    // Layer 2
    k_agg<<<agrid, ab>>>(h, agg, N);
    k_gemm<48, 3, false><<<(N + 63) / 64, 256>>>(agg, h, w2l, w2r, b2, out, N);
}

// round 9
// speedup vs baseline: 1.1159x; 1.1159x over previous
#include <cuda_runtime.h>

#define N_NODES 50000
#define N_EDGES 800000
#define F 96

// Scratch (device globals; no allocation allowed)
__device__ int   g_deg[N_NODES];
__device__ int   g_off[N_NODES + 1];
__device__ int   g_cur[N_NODES];
__device__ int   g_srcs[N_EDGES];
__device__ float g_p1[N_NODES * 192];   // x @ [w1l;w1r]^T
__device__ float g_h[N_NODES * F];      // layer-1 output
__device__ float g_p2[N_NODES * 96];    // h @ [w2l;w2r]^T

// ---------------- CSR build ----------------
__global__ void k_zero(int n) {
    int i = blockIdx.x * blockDim.x + threadIdx.x;
    if (i < n) g_deg[i] = 0;
}

__global__ void k_hist(const int* __restrict__ ei, int E) {
    int e = blockIdx.x * blockDim.x + threadIdx.x;
    if (e < E) {
        int dst = ei[E + e];
        if ((unsigned)dst < N_NODES) atomicAdd(&g_deg[dst], 1);
    }
}

__global__ void k_scan(int n, int E) {
    __shared__ int sh[1024];
    int t = threadIdx.x;
    int C = (n + 1023) / 1024;
    int base = t * C;
    int end = min(base + C, n);
    int s = 0;
    for (int i = base; i < end; i++) s += g_deg[i];
    sh[t] = s;
    __syncthreads();
    for (int d = 1; d < 1024; d <<= 1) {
        int v = (t >= d) ? sh[t - d] : 0;
        __syncthreads();
        if (t >= d) sh[t] += v;
        __syncthreads();
    }
    int run = (t == 0) ? 0 : sh[t - 1];
    for (int i = base; i < end; i++) {
        g_off[i] = run;
        g_cur[i] = run;
        run += g_deg[i];
    }
    if (t == 0) g_off[n] = E;
}

__global__ void k_scatter(const int* __restrict__ ei, int E) {
    int e = blockIdx.x * blockDim.x + threadIdx.x;
    if (e < E) {
        int src = ei[e];
        int dst = ei[E + e];
        if ((unsigned)dst < N_NODES && (unsigned)src < N_NODES) {
            int p = atomicAdd(&g_cur[dst], 1);
            if ((unsigned)p < N_EDGES) g_srcs[p] = src;
        }
    }
}

// ---------------- packed f32x2 FMA helpers ----------------
__device__ __forceinline__ unsigned long long dup2(float a) {
    unsigned long long r;
    asm("mov.b64 %0, {%1, %1};" : "=l"(r) : "f"(a));
    return r;
}
__device__ __forceinline__ void ffma2(unsigned long long& c, unsigned long long a,
                                      unsigned long long b) {
    asm("fma.rn.f32x2 %0, %1, %2, %0;" : "+l"(c) : "l"(a), "l"(b));
}

// ---------------- fused projection GEMM ----------------
// P[i][n] = sum_k A[i][k] * W[n][k],  W = concat rows(Wa [0..BN/2), Wb [BN/2..BN))
// A: [M][96] row-major. BM=128, BK=16, 256 threads = 16(tx over N) x 16(ty over M).
// TM=8 rows/thread, TN2 = (BN/16)/2 float2-pairs per thread.
template <int BN, int TN2>
__global__ __launch_bounds__(256) void k_proj(const float* __restrict__ A,
                                              const float* __restrict__ Wa,
                                              const float* __restrict__ Wb,
                                              float* __restrict__ P, int M) {
    const int BM = 128, BK = 16, TM = 8;
    const int TN = TN2 * 2;
    __shared__ float As[BK][BM + 4];
    __shared__ float Ws[BK][BN];

    int tid = threadIdx.x;
    int tx = tid & 15;
    int ty = tid >> 4;
    int rowBase = blockIdx.x * BM;

    unsigned long long acc[TM][TN2];
#pragma unroll
    for (int m = 0; m < TM; m++)
#pragma unroll
        for (int j = 0; j < TN2; j++) acc[m][j] = 0ull;

    for (int k0 = 0; k0 < F; k0 += BK) {
        // A tile: 128 rows x 16 k, float4 along k. 512 vec loads / 256 thr = 2 each.
#pragma unroll
        for (int l = 0; l < 2; l++) {
            int v = tid + l * 256;
            int r = v >> 2;
            int kg = v & 3;
            int row = rowBase + r;
            float4 val = make_float4(0.f, 0.f, 0.f, 0.f);
            if (row < M) val = *(const float4*)&A[row * F + k0 + kg * 4];
            As[kg * 4 + 0][r] = val.x;
            As[kg * 4 + 1][r] = val.y;
            As[kg * 4 + 2][r] = val.z;
            As[kg * 4 + 3][r] = val.w;
        }
        // W tile: BN rows x 16 k
        for (int v = tid; v < BN * 4; v += 256) {
            int n = v >> 2;
            int kg = v & 3;
            const float* Wrow = (n < BN / 2) ? (Wa + n * F) : (Wb + (n - BN / 2) * F);
            float4 val = *(const float4*)&Wrow[k0 + kg * 4];
            Ws[kg * 4 + 0][n] = val.x;
            Ws[kg * 4 + 1][n] = val.y;
            Ws[kg * 4 + 2][n] = val.z;
            Ws[kg * 4 + 3][n] = val.w;
        }
        __syncthreads();

#pragma unroll
        for (int kk = 0; kk < BK; kk++) {
            float4 a0 = *(const float4*)&As[kk][ty * TM];
            float4 a1 = *(const float4*)&As[kk][ty * TM + 4];
            float a[TM] = {a0.x, a0.y, a0.z, a0.w, a1.x, a1.y, a1.z, a1.w};
            unsigned long long wv[TN2];
            const unsigned long long* wp =
                (const unsigned long long*)&Ws[kk][tx * TN];
#pragma unroll
            for (int j = 0; j < TN2; j++) wv[j] = wp[j];
#pragma unroll
            for (int m = 0; m < TM; m++) {
                unsigned long long ad = dup2(a[m]);
#pragma unroll
                for (int j = 0; j < TN2; j++) ffma2(acc[m][j], ad, wv[j]);
            }
        }
        __syncthreads();
    }

#pragma unroll
    for (int m = 0; m < TM; m++) {
        int row = rowBase + ty * TM + m;
        if (row < M) {
            unsigned long long* op =
                (unsigned long long*)&P[row * BN + tx * TN];
#pragma unroll
            for (int j = 0; j < TN2; j++) op[j] = acc[m][j];
        }
    }
}

// ---------------- fused aggregation + residual + bias (+ReLU) ----------------
// out[i][f] = act( mean_{src in N(i)} P[src][f]  +  P[i][FAGG+f] + bias[f] )
template <int FAGG, int STRIDE, bool RELU>
__global__ void k_aggfuse(const float* __restrict__ P,
                          const float* __restrict__ bias,
                          float* __restrict__ out, int n) {
    int node = blockIdx.x * blockDim.y + threadIdx.y;
    int f = threadIdx.x;
    if (node >= n) return;
    int o0 = g_off[node];
    int o1 = g_off[node + 1];
    float s = 0.f;
    for (int j = o0; j < o1; j++) {
        int src = __ldg(&g_srcs[j]);
        s += __ldg(&P[src * STRIDE + f]);
    }
    int d = o1 - o0;
    float mean = (d > 0) ? s / (float)d : 0.0f;
    float v = mean + P[node * STRIDE + FAGG + f] + bias[f];
    if (RELU) v = fmaxf(v, 0.f);
    out[node * FAGG + f] = v;
}

extern "C" void kernel_launch(void* const* d_in, const int* in_sizes, int n_in,
                              void* d_out, int out_size) {
    const float* x   = (const float*)d_in[0];
    const int*   ei  = (const int*)d_in[1];     // int32 edge_index [2, E]
    const float* w1l = (const float*)d_in[2];
    const float* b1  = (const float*)d_in[3];
    const float* w1r = (const float*)d_in[4];
    const float* w2l = (const float*)d_in[5];
    const float* b2  = (const float*)d_in[6];
    const float* w2r = (const float*)d_in[7];
    float* out = (float*)d_out;

    const int N = N_NODES;
    const int E = in_sizes[1] / 2;

    void *p_p1, *p_p2, *p_h;
    cudaGetSymbolAddress(&p_p1, g_p1);
    cudaGetSymbolAddress(&p_p2, g_p2);
    cudaGetSymbolAddress(&p_h, g_h);
    float* P1 = (float*)p_p1;
    float* P2 = (float*)p_p2;
    float* h  = (float*)p_h;

    // CSR build
    k_zero<<<(N + 255) / 256, 256>>>(N);
    k_hist<<<(E + 255) / 256, 256>>>(ei, E);
    k_scan<<<1, 1024>>>(N, E);
    k_scatter<<<(E + 255) / 256, 256>>>(ei, E);

    int ggrid = (N + 127) / 128;

    // Layer 1: project (96 -> 192), aggregate projected, fuse residual+bias+relu
    k_proj<192, 6><<<ggrid, 256>>>(x, w1l, w1r, P1, N);
    k_aggfuse<96, 192, true><<<(N + 3) / 4, dim3(96, 4)>>>(P1, b1, h, N);

    // Layer 2: project (96 -> 96), aggregate first 48 cols, fuse residual+bias
    k_proj<96, 3><<<ggrid, 256>>>(h, w2l, w2r, P2, N);
    k_aggfuse<48, 96, false><<<(N + 7) / 8, dim3(48, 8)>>>(P2, b2, out, N);
}

// round 10
// speedup vs baseline: 1.1890x; 1.0655x over previous
#include <cuda_runtime.h>

#define N_NODES 50000
#define N_EDGES 800000
#define F 96

// Scratch (device globals; no allocation allowed)
__device__ int   g_deg[N_NODES];
__device__ int   g_off[N_NODES + 1];
__device__ int   g_cur[N_NODES];
__device__ int   g_srcs[N_EDGES];
__device__ float g_p1[N_NODES * 192];   // x @ [w1l;w1r]^T
__device__ float g_h[N_NODES * F];      // layer-1 output
__device__ float g_p2[N_NODES * 96];    // h @ [w2l;w2r]^T

// ---------------- CSR build ----------------
__global__ void k_zero(int n) {
    int i = blockIdx.x * blockDim.x + threadIdx.x;
    if (i < n) g_deg[i] = 0;
}

__global__ void k_hist(const int* __restrict__ ei, int E) {
    int e = blockIdx.x * blockDim.x + threadIdx.x;
    if (e < E) {
        int dst = ei[E + e];
        if ((unsigned)dst < N_NODES) atomicAdd(&g_deg[dst], 1);
    }
}

__global__ void k_scan(int n, int E) {
    __shared__ int sh[1024];
    int t = threadIdx.x;
    int C = (n + 1023) / 1024;
    int base = t * C;
    int end = min(base + C, n);
    int s = 0;
    for (int i = base; i < end; i++) s += g_deg[i];
    sh[t] = s;
    __syncthreads();
    for (int d = 1; d < 1024; d <<= 1) {
        int v = (t >= d) ? sh[t - d] : 0;
        __syncthreads();
        if (t >= d) sh[t] += v;
        __syncthreads();
    }
    int run = (t == 0) ? 0 : sh[t - 1];
    for (int i = base; i < end; i++) {
        g_off[i] = run;
        g_cur[i] = run;
        run += g_deg[i];
    }
    if (t == 0) g_off[n] = E;
}

__global__ void k_scatter(const int* __restrict__ ei, int E) {
    int e = blockIdx.x * blockDim.x + threadIdx.x;
    if (e < E) {
        int src = ei[e];
        int dst = ei[E + e];
        if ((unsigned)dst < N_NODES && (unsigned)src < N_NODES) {
            int p = atomicAdd(&g_cur[dst], 1);
            if ((unsigned)p < N_EDGES) g_srcs[p] = src;
        }
    }
}

// ---------------- packed f32x2 FMA helpers ----------------
__device__ __forceinline__ unsigned long long dup2(float a) {
    unsigned long long r;
    asm("mov.b64 %0, {%1, %1};" : "=l"(r) : "f"(a));
    return r;
}
__device__ __forceinline__ void ffma2(unsigned long long& c, unsigned long long a,
                                      unsigned long long b) {
    asm("fma.rn.f32x2 %0, %1, %2, %0;" : "+l"(c) : "l"(a), "l"(b));
}

// ---------------- fused projection GEMM ----------------
// P[i][n] = sum_k A[i][k] * W[n][k],  W = concat rows(Wa [0..BN/2), Wb [BN/2..BN))
// A: [M][96] row-major. BM=128, BK=16, 256 threads = 16(tx over N) x 16(ty over M).
// TM=8 rows/thread, TN2 = (BN/16)/2 float2-pairs per thread.
template <int BN, int TN2>
__global__ __launch_bounds__(256) void k_proj(const float* __restrict__ A,
                                              const float* __restrict__ Wa,
                                              const float* __restrict__ Wb,
                                              float* __restrict__ P, int M) {
    const int BM = 128, BK = 16, TM = 8;
    const int TN = TN2 * 2;
    __shared__ float As[BK][BM + 4];
    __shared__ float Ws[BK][BN];

    int tid = threadIdx.x;
    int tx = tid & 15;
    int ty = tid >> 4;
    int rowBase = blockIdx.x * BM;

    unsigned long long acc[TM][TN2];
#pragma unroll
    for (int m = 0; m < TM; m++)
#pragma unroll
        for (int j = 0; j < TN2; j++) acc[m][j] = 0ull;

    for (int k0 = 0; k0 < F; k0 += BK) {
        // A tile: 128 rows x 16 k, float4 along k. 512 vec loads / 256 thr = 2 each.
#pragma unroll
        for (int l = 0; l < 2; l++) {
            int v = tid + l * 256;
            int r = v >> 2;
            int kg = v & 3;
            int row = rowBase + r;
            float4 val = make_float4(0.f, 0.f, 0.f, 0.f);
            if (row < M) val = *(const float4*)&A[row * F + k0 + kg * 4];
            As[kg * 4 + 0][r] = val.x;
            As[kg * 4 + 1][r] = val.y;
            As[kg * 4 + 2][r] = val.z;
            As[kg * 4 + 3][r] = val.w;
        }
        // W tile: BN rows x 16 k
        for (int v = tid; v < BN * 4; v += 256) {
            int n = v >> 2;
            int kg = v & 3;
            const float* Wrow = (n < BN / 2) ? (Wa + n * F) : (Wb + (n - BN / 2) * F);
            float4 val = *(const float4*)&Wrow[k0 + kg * 4];
            Ws[kg * 4 + 0][n] = val.x;
            Ws[kg * 4 + 1][n] = val.y;
            Ws[kg * 4 + 2][n] = val.z;
            Ws[kg * 4 + 3][n] = val.w;
        }
        __syncthreads();

#pragma unroll
        for (int kk = 0; kk < BK; kk++) {
            float4 a0 = *(const float4*)&As[kk][ty * TM];
            float4 a1 = *(const float4*)&As[kk][ty * TM + 4];
            float a[TM] = {a0.x, a0.y, a0.z, a0.w, a1.x, a1.y, a1.z, a1.w};
            unsigned long long wv[TN2];
            if constexpr ((TN2 & 1) == 0) {
                const ulonglong2* wp = (const ulonglong2*)&Ws[kk][tx * TN];
#pragma unroll
                for (int j = 0; j < TN2 / 2; j++) {
                    ulonglong2 t = wp[j];
                    wv[2 * j] = t.x;
                    wv[2 * j + 1] = t.y;
                }
            } else {
                const unsigned long long* wp =
                    (const unsigned long long*)&Ws[kk][tx * TN];
#pragma unroll
                for (int j = 0; j < TN2; j++) wv[j] = wp[j];
            }
#pragma unroll
            for (int m = 0; m < TM; m++) {
                unsigned long long ad = dup2(a[m]);
#pragma unroll
                for (int j = 0; j < TN2; j++) ffma2(acc[m][j], ad, wv[j]);
            }
        }
        __syncthreads();
    }

#pragma unroll
    for (int m = 0; m < TM; m++) {
        int row = rowBase + ty * TM + m;
        if (row < M) {
            unsigned long long* op =
                (unsigned long long*)&P[row * BN + tx * TN];
#pragma unroll
            for (int j = 0; j < TN2; j++) op[j] = acc[m][j];
        }
    }
}

// ---------------- fused aggregation + residual + bias (+ReLU) ----------------
// out[i][f] = act( mean_{src in N(i)} P[src][f]  +  P[i][FAGG+f] + bias[f] )
template <int FAGG, int STRIDE, bool RELU>
__global__ void k_aggfuse(const float* __restrict__ P,
                          const float* __restrict__ bias,
                          float* __restrict__ out, int n) {
    int node = blockIdx.x * blockDim.y + threadIdx.y;
    int f = threadIdx.x;
    if (node >= n) return;
    int o0 = g_off[node];
    int o1 = g_off[node + 1];
    float s0 = 0.f, s1 = 0.f;
    int j = o0;
    for (; j + 2 <= o1; j += 2) {
        int a = __ldg(&g_srcs[j]);
        int b = __ldg(&g_srcs[j + 1]);
        s0 += __ldg(&P[a * STRIDE + f]);
        s1 += __ldg(&P[b * STRIDE + f]);
    }
    if (j < o1) {
        int a = __ldg(&g_srcs[j]);
        s0 += __ldg(&P[a * STRIDE + f]);
    }
    int d = o1 - o0;
    float mean = (d > 0) ? (s0 + s1) / (float)d : 0.0f;
    float v = mean + P[node * STRIDE + FAGG + f] + bias[f];
    if (RELU) v = fmaxf(v, 0.f);
    out[node * FAGG + f] = v;
}

extern "C" void kernel_launch(void* const* d_in, const int* in_sizes, int n_in,
                              void* d_out, int out_size) {
    const float* x   = (const float*)d_in[0];
    const int*   ei  = (const int*)d_in[1];     // int32 edge_index [2, E]
    const float* w1l = (const float*)d_in[2];
    const float* b1  = (const float*)d_in[3];
    const float* w1r = (const float*)d_in[4];
    const float* w2l = (const float*)d_in[5];
    const float* b2  = (const float*)d_in[6];
    const float* w2r = (const float*)d_in[7];
    float* out = (float*)d_out;

    const int N = N_NODES;
    const int E = in_sizes[1] / 2;

    void *p_p1, *p_p2, *p_h;
    cudaGetSymbolAddress(&p_p1, g_p1);
    cudaGetSymbolAddress(&p_p2, g_p2);
    cudaGetSymbolAddress(&p_h, g_h);
    float* P1 = (float*)p_p1;
    float* P2 = (float*)p_p2;
    float* h  = (float*)p_h;

    // Lazy-create side stream + events (first call is the uncaptured
    // correctness run, so creation happens outside graph capture).
    static cudaStream_t s_side = nullptr;
    static cudaEvent_t ev_fork = nullptr, ev_join = nullptr;
    if (s_side == nullptr) {
        cudaStreamCreateWithFlags(&s_side, cudaStreamNonBlocking);
        cudaEventCreateWithFlags(&ev_fork, cudaEventDisableTiming);
        cudaEventCreateWithFlags(&ev_join, cudaEventDisableTiming);
    }

    // Fork: CSR build on side stream, proj1 concurrently on main stream.
    cudaEventRecord(ev_fork, 0);
    cudaStreamWaitEvent(s_side, ev_fork, 0);

    k_zero<<<(N + 255) / 256, 256, 0, s_side>>>(N);
    k_hist<<<(E + 255) / 256, 256, 0, s_side>>>(ei, E);
    k_scan<<<1, 1024, 0, s_side>>>(N, E);
    k_scatter<<<(E + 255) / 256, 256, 0, s_side>>>(ei, E);
    cudaEventRecord(ev_join, s_side);

    int ggrid = (N + 127) / 128;

    // Layer 1 projection (independent of edges) overlaps CSR build.
    k_proj<192, 6><<<ggrid, 256>>>(x, w1l, w1r, P1, N);

    // Join: aggregation needs both CSR and P1.
    cudaStreamWaitEvent(0, ev_join, 0);

    k_aggfuse<96, 192, true><<<(N + 3) / 4, dim3(96, 4)>>>(P1, b1, h, N);

    // Layer 2
    k_proj<96, 3><<<ggrid, 256>>>(h, w2l, w2r, P2, N);
    k_aggfuse<48, 96, false><<<(N + 7) / 8, dim3(48, 8)>>>(P2, b2, out, N);
}

// round 11
// speedup vs baseline: 1.1932x; 1.0035x over previous
#include <cuda_runtime.h>

#define N_NODES 50000
#define N_EDGES 800000
#define F 96

// Scratch (device globals; no allocation allowed)
__device__ int   g_deg[N_NODES];
__device__ int   g_off[N_NODES + 1];
__device__ int   g_cur[N_NODES];
__device__ int   g_srcs[N_EDGES];
__device__ float g_p1[N_NODES * 192];   // x @ [w1l;w1r]^T
__device__ float g_h[N_NODES * F];      // layer-1 output
__device__ float g_p2[N_NODES * 96];    // h @ [w2l;w2r]^T

// ---------------- CSR build ----------------
__global__ void k_zero(int n) {
    int i = blockIdx.x * blockDim.x + threadIdx.x;
    if (i < n) g_deg[i] = 0;
}

// 4 edges per thread for MLP
__global__ void k_hist(const int* __restrict__ ei, int E) {
    int base = (blockIdx.x * blockDim.x + threadIdx.x) * 4;
#pragma unroll
    for (int u = 0; u < 4; u++) {
        int e = base + u;
        if (e < E) {
            int dst = ei[E + e];
            if ((unsigned)dst < N_NODES) atomicAdd(&g_deg[dst], 1);
        }
    }
}

__global__ void k_scan(int n, int E) {
    __shared__ int sh[1024];
    int t = threadIdx.x;
    int C = (n + 1023) / 1024;
    int base = t * C;
    int end = min(base + C, n);
    int s = 0;
    for (int i = base; i < end; i++) s += g_deg[i];
    sh[t] = s;
    __syncthreads();
    for (int d = 1; d < 1024; d <<= 1) {
        int v = (t >= d) ? sh[t - d] : 0;
        __syncthreads();
        if (t >= d) sh[t] += v;
        __syncthreads();
    }
    int run = (t == 0) ? 0 : sh[t - 1];
    for (int i = base; i < end; i++) {
        g_off[i] = run;
        g_cur[i] = run;
        run += g_deg[i];
    }
    if (t == 0) g_off[n] = E;
}

__global__ void k_scatter(const int* __restrict__ ei, int E) {
    int base = (blockIdx.x * blockDim.x + threadIdx.x) * 4;
#pragma unroll
    for (int u = 0; u < 4; u++) {
        int e = base + u;
        if (e < E) {
            int src = ei[e];
            int dst = ei[E + e];
            if ((unsigned)dst < N_NODES && (unsigned)src < N_NODES) {
                int p = atomicAdd(&g_cur[dst], 1);
                if ((unsigned)p < N_EDGES) g_srcs[p] = src;
            }
        }
    }
}

// ---------------- packed f32x2 FMA helpers ----------------
__device__ __forceinline__ unsigned long long dup2(float a) {
    unsigned long long r;
    asm("mov.b64 %0, {%1, %1};" : "=l"(r) : "f"(a));
    return r;
}
__device__ __forceinline__ void ffma2(unsigned long long& c, unsigned long long a,
                                      unsigned long long b) {
    asm("fma.rn.f32x2 %0, %1, %2, %0;" : "+l"(c) : "l"(a), "l"(b));
}

// ---------------- fused projection GEMM ----------------
// P[i][n] = sum_k A[i][k] * W[n][k],  W = concat rows(Wa [0..BN/2), Wb [BN/2..BN))
// A: [M][96] row-major. BM=128, BK=16, 512 threads = 16(tx over N) x 32(ty over M).
// TM=4 rows/thread, TN2 = (BN/16)/2 float2-pairs per thread.
template <int BN, int TN2>
__global__ __launch_bounds__(512) void k_proj(const float* __restrict__ A,
                                              const float* __restrict__ Wa,
                                              const float* __restrict__ Wb,
                                              float* __restrict__ P, int M) {
    const int BM = 128, BK = 16, TM = 4;
    const int TN = TN2 * 2;
    __shared__ float As[BK][BM + 4];
    __shared__ float Ws[BK][BN];

    int tid = threadIdx.x;
    int tx = tid & 15;
    int ty = tid >> 4;
    int rowBase = blockIdx.x * BM;

    unsigned long long acc[TM][TN2];
#pragma unroll
    for (int m = 0; m < TM; m++)
#pragma unroll
        for (int j = 0; j < TN2; j++) acc[m][j] = 0ull;

    for (int k0 = 0; k0 < F; k0 += BK) {
        // A tile: 128 rows x 16 k, float4 along k. 512 vec loads / 512 thr = 1 each.
        {
            int v = tid;
            int r = v >> 2;
            int kg = v & 3;
            int row = rowBase + r;
            float4 val = make_float4(0.f, 0.f, 0.f, 0.f);
            if (row < M) val = *(const float4*)&A[row * F + k0 + kg * 4];
            As[kg * 4 + 0][r] = val.x;
            As[kg * 4 + 1][r] = val.y;
            As[kg * 4 + 2][r] = val.z;
            As[kg * 4 + 3][r] = val.w;
        }
        // W tile: BN rows x 16 k
        for (int v = tid; v < BN * 4; v += 512) {
            int n = v >> 2;
            int kg = v & 3;
            const float* Wrow = (n < BN / 2) ? (Wa + n * F) : (Wb + (n - BN / 2) * F);
            float4 val = *(const float4*)&Wrow[k0 + kg * 4];
            Ws[kg * 4 + 0][n] = val.x;
            Ws[kg * 4 + 1][n] = val.y;
            Ws[kg * 4 + 2][n] = val.z;
            Ws[kg * 4 + 3][n] = val.w;
        }
        __syncthreads();

#pragma unroll
        for (int kk = 0; kk < BK; kk++) {
            float4 a0 = *(const float4*)&As[kk][ty * TM];
            float a[TM] = {a0.x, a0.y, a0.z, a0.w};
            unsigned long long wv[TN2];
            if constexpr ((TN2 & 1) == 0) {
                const ulonglong2* wp = (const ulonglong2*)&Ws[kk][tx * TN];
#pragma unroll
                for (int j = 0; j < TN2 / 2; j++) {
                    ulonglong2 t = wp[j];
                    wv[2 * j] = t.x;
                    wv[2 * j + 1] = t.y;
                }
            } else {
                const unsigned long long* wp =
                    (const unsigned long long*)&Ws[kk][tx * TN];
#pragma unroll
                for (int j = 0; j < TN2; j++) wv[j] = wp[j];
            }
#pragma unroll
            for (int m = 0; m < TM; m++) {
                unsigned long long ad = dup2(a[m]);
#pragma unroll
                for (int j = 0; j < TN2; j++) ffma2(acc[m][j], ad, wv[j]);
            }
        }
        __syncthreads();
    }

#pragma unroll
    for (int m = 0; m < TM; m++) {
        int row = rowBase + ty * TM + m;
        if (row < M) {
            unsigned long long* op =
                (unsigned long long*)&P[row * BN + tx * TN];
#pragma unroll
            for (int j = 0; j < TN2; j++) op[j] = acc[m][j];
        }
    }
}

// ---------------- fused aggregation + residual + bias (+ReLU) ----------------
// out[i][f] = act( mean_{src in N(i)} P[src][f]  +  P[i][FAGG+f] + bias[f] )
template <int FAGG, int STRIDE, bool RELU>
__global__ void k_aggfuse(const float* __restrict__ P,
                          const float* __restrict__ bias,
                          float* __restrict__ out, int n) {
    int node = blockIdx.x * blockDim.y + threadIdx.y;
    int f = threadIdx.x;
    if (node >= n) return;
    int o0 = g_off[node];
    int o1 = g_off[node + 1];
    float s0 = 0.f, s1 = 0.f, s2 = 0.f, s3 = 0.f;
    int j = o0;
    for (; j + 4 <= o1; j += 4) {
        int a = __ldg(&g_srcs[j]);
        int b = __ldg(&g_srcs[j + 1]);
        int c = __ldg(&g_srcs[j + 2]);
        int d = __ldg(&g_srcs[j + 3]);
        s0 += __ldg(&P[a * STRIDE + f]);
        s1 += __ldg(&P[b * STRIDE + f]);
        s2 += __ldg(&P[c * STRIDE + f]);
        s3 += __ldg(&P[d * STRIDE + f]);
    }
    for (; j < o1; j++) {
        int a = __ldg(&g_srcs[j]);
        s0 += __ldg(&P[a * STRIDE + f]);
    }
    int d = o1 - o0;
    float mean = (d > 0) ? ((s0 + s1) + (s2 + s3)) / (float)d : 0.0f;
    float v = mean + P[node * STRIDE + FAGG + f] + bias[f];
    if (RELU) v = fmaxf(v, 0.f);
    out[node * FAGG + f] = v;
}

extern "C" void kernel_launch(void* const* d_in, const int* in_sizes, int n_in,
                              void* d_out, int out_size) {
    const float* x   = (const float*)d_in[0];
    const int*   ei  = (const int*)d_in[1];     // int32 edge_index [2, E]
    const float* w1l = (const float*)d_in[2];
    const float* b1  = (const float*)d_in[3];
    const float* w1r = (const float*)d_in[4];
    const float* w2l = (const float*)d_in[5];
    const float* b2  = (const float*)d_in[6];
    const float* w2r = (const float*)d_in[7];
    float* out = (float*)d_out;

    const int N = N_NODES;
    const int E = in_sizes[1] / 2;

    void *p_p1, *p_p2, *p_h;
    cudaGetSymbolAddress(&p_p1, g_p1);
    cudaGetSymbolAddress(&p_p2, g_p2);
    cudaGetSymbolAddress(&p_h, g_h);
    float* P1 = (float*)p_p1;
    float* P2 = (float*)p_p2;
    float* h  = (float*)p_h;

    // Lazy-create side stream + events (first call is the uncaptured
    // correctness run, so creation happens outside graph capture).
    static cudaStream_t s_side = nullptr;
    static cudaEvent_t ev_fork = nullptr, ev_join = nullptr;
    if (s_side == nullptr) {
        cudaStreamCreateWithFlags(&s_side, cudaStreamNonBlocking);
        cudaEventCreateWithFlags(&ev_fork, cudaEventDisableTiming);
        cudaEventCreateWithFlags(&ev_join, cudaEventDisableTiming);
    }

    // Fork: CSR build on side stream, proj1 concurrently on main stream.
    cudaEventRecord(ev_fork, 0);
    cudaStreamWaitEvent(s_side, ev_fork, 0);

    int e4 = (E + 3) / 4;
    k_zero<<<(N + 255) / 256, 256, 0, s_side>>>(N);
    k_hist<<<(e4 + 255) / 256, 256, 0, s_side>>>(ei, E);
    k_scan<<<1, 1024, 0, s_side>>>(N, E);
    k_scatter<<<(e4 + 255) / 256, 256, 0, s_side>>>(ei, E);
    cudaEventRecord(ev_join, s_side);

    int ggrid = (N + 127) / 128;

    // Layer 1 projection (independent of edges) overlaps CSR build.
    k_proj<192, 6><<<ggrid, 512>>>(x, w1l, w1r, P1, N);

    // Join: aggregation needs both CSR and P1.
    cudaStreamWaitEvent(0, ev_join, 0);

    k_aggfuse<96, 192, true><<<(N + 3) / 4, dim3(96, 4)>>>(P1, b1, h, N);

    // Layer 2
    k_proj<96, 3><<<ggrid, 512>>>(h, w2l, w2r, P2, N);
    k_aggfuse<48, 96, false><<<(N + 7) / 8, dim3(48, 8)>>>(P2, b2, out, N);
}

// round 12
// speedup vs baseline: 1.3761x; 1.1533x over previous
#include <cuda_runtime.h>
#include <cuda_fp16.h>

#define N_NODES 50000
#define N_EDGES 800000
#define F 96

// Scratch (device globals; no allocation allowed)
__device__ int     g_deg[N_NODES];
__device__ int     g_off[N_NODES + 1];
__device__ int     g_cur[N_NODES];
__device__ int     g_srcs[N_EDGES];
__device__ __half2 g_g1h[N_NODES * 48];   // half2: x @ w1l^T   (gather half)
__device__ float   g_p1r[N_NODES * 96];   // fp32:  x @ w1r^T   (residual half)
__device__ __half2 g_g2h[N_NODES * 24];   // half2: h @ w2l^T
__device__ float   g_p2r[N_NODES * 48];   // fp32:  h @ w2r^T
__device__ float   g_h[N_NODES * F];      // layer-1 output

// ---------------- CSR build ----------------
// 4 edges per thread for MLP
__global__ void k_hist(const int* __restrict__ ei, int E) {
    int base = (blockIdx.x * blockDim.x + threadIdx.x) * 4;
#pragma unroll
    for (int u = 0; u < 4; u++) {
        int e = base + u;
        if (e < E) {
            int dst = ei[E + e];
            if ((unsigned)dst < N_NODES) atomicAdd(&g_deg[dst], 1);
        }
    }
}

__global__ void k_scan(int n, int E) {
    __shared__ int sh[1024];
    int t = threadIdx.x;
    int C = (n + 1023) / 1024;
    int base = t * C;
    int end = min(base + C, n);
    int s = 0;
    for (int i = base; i < end; i++) s += g_deg[i];
    sh[t] = s;
    __syncthreads();
    for (int d = 1; d < 1024; d <<= 1) {
        int v = (t >= d) ? sh[t - d] : 0;
        __syncthreads();
        if (t >= d) sh[t] += v;
        __syncthreads();
    }
    int run = (t == 0) ? 0 : sh[t - 1];
    for (int i = base; i < end; i++) {
        g_off[i] = run;
        g_cur[i] = run;
        run += g_deg[i];
    }
    if (t == 0) g_off[n] = E;
}

__global__ void k_scatter(const int* __restrict__ ei, int E) {
    int base = (blockIdx.x * blockDim.x + threadIdx.x) * 4;
#pragma unroll
    for (int u = 0; u < 4; u++) {
        int e = base + u;
        if (e < E) {
            int src = ei[e];
            int dst = ei[E + e];
            if ((unsigned)dst < N_NODES && (unsigned)src < N_NODES) {
                int p = atomicAdd(&g_cur[dst], 1);
                if ((unsigned)p < N_EDGES) g_srcs[p] = src;
            }
        }
    }
}

// ---------------- packed f32x2 FMA helpers ----------------
__device__ __forceinline__ unsigned long long dup2(float a) {
    unsigned long long r;
    asm("mov.b64 %0, {%1, %1};" : "=l"(r) : "f"(a));
    return r;
}
__device__ __forceinline__ void ffma2(unsigned long long& c, unsigned long long a,
                                      unsigned long long b) {
    asm("fma.rn.f32x2 %0, %1, %2, %0;" : "+l"(c) : "l"(a), "l"(b));
}
__device__ __forceinline__ void unpack2(unsigned long long v, float& lo, float& hi) {
    asm("mov.b64 {%0, %1}, %2;" : "=f"(lo), "=f"(hi) : "l"(v));
}

// ---------------- fused projection GEMM with split epilogue ----------------
// Cols [0, BN/2): Wa projection -> half2 gather buffer GH (row stride BN/4 half2)
// Cols [BN/2, BN): Wb projection -> fp32 residual buffer PR (row stride BN/2)
// BM=128, BK=16, 512 threads = 16(tx) x 32(ty), TM=4, TN=2*TN2.
template <int BN, int TN2>
__global__ __launch_bounds__(512) void k_proj(const float* __restrict__ A,
                                              const float* __restrict__ Wa,
                                              const float* __restrict__ Wb,
                                              __half2* __restrict__ GH,
                                              float* __restrict__ PR, int M) {
    const int BM = 128, BK = 16, TM = 4;
    const int TN = TN2 * 2;
    const int HALF_TX = (BN / 2) / TN;   // tx below this -> gather half
    __shared__ float As[BK][BM + 4];
    __shared__ float Ws[BK][BN];

    int tid = threadIdx.x;
    int tx = tid & 15;
    int ty = tid >> 4;
    int rowBase = blockIdx.x * BM;

    unsigned long long acc[TM][TN2];
#pragma unroll
    for (int m = 0; m < TM; m++)
#pragma unroll
        for (int j = 0; j < TN2; j++) acc[m][j] = 0ull;

    for (int k0 = 0; k0 < F; k0 += BK) {
        {
            int v = tid;
            int r = v >> 2;
            int kg = v & 3;
            int row = rowBase + r;
            float4 val = make_float4(0.f, 0.f, 0.f, 0.f);
            if (row < M) val = *(const float4*)&A[row * F + k0 + kg * 4];
            As[kg * 4 + 0][r] = val.x;
            As[kg * 4 + 1][r] = val.y;
            As[kg * 4 + 2][r] = val.z;
            As[kg * 4 + 3][r] = val.w;
        }
        for (int v = tid; v < BN * 4; v += 512) {
            int n = v >> 2;
            int kg = v & 3;
            const float* Wrow = (n < BN / 2) ? (Wa + n * F) : (Wb + (n - BN / 2) * F);
            float4 val = *(const float4*)&Wrow[k0 + kg * 4];
            Ws[kg * 4 + 0][n] = val.x;
            Ws[kg * 4 + 1][n] = val.y;
            Ws[kg * 4 + 2][n] = val.z;
            Ws[kg * 4 + 3][n] = val.w;
        }
        __syncthreads();

#pragma unroll
        for (int kk = 0; kk < BK; kk++) {
            float4 a0 = *(const float4*)&As[kk][ty * TM];
            float a[TM] = {a0.x, a0.y, a0.z, a0.w};
            unsigned long long wv[TN2];
            if constexpr ((TN2 & 1) == 0) {
                const ulonglong2* wp = (const ulonglong2*)&Ws[kk][tx * TN];
#pragma unroll
                for (int j = 0; j < TN2 / 2; j++) {
                    ulonglong2 t = wp[j];
                    wv[2 * j] = t.x;
                    wv[2 * j + 1] = t.y;
                }
            } else {
                const unsigned long long* wp =
                    (const unsigned long long*)&Ws[kk][tx * TN];
#pragma unroll
                for (int j = 0; j < TN2; j++) wv[j] = wp[j];
            }
#pragma unroll
            for (int m = 0; m < TM; m++) {
                unsigned long long ad = dup2(a[m]);
#pragma unroll
                for (int j = 0; j < TN2; j++) ffma2(acc[m][j], ad, wv[j]);
            }
        }
        __syncthreads();
    }

#pragma unroll
    for (int m = 0; m < TM; m++) {
        int row = rowBase + ty * TM + m;
        if (row < M) {
            if (tx < HALF_TX) {
                // gather half: convert each f32 pair to half2
                __half2* op = &GH[row * (BN / 4) + (tx * TN) / 2];
#pragma unroll
                for (int j = 0; j < TN2; j++) {
                    float lo, hi;
                    unpack2(acc[m][j], lo, hi);
                    op[j] = __floats2half2_rn(lo, hi);
                }
            } else {
                // residual half: fp32
                int c = tx * TN - BN / 2;
                unsigned long long* op =
                    (unsigned long long*)&PR[row * (BN / 2) + c];
#pragma unroll
                for (int j = 0; j < TN2; j++) op[j] = acc[m][j];
            }
        }
    }
}

// ---------------- fused aggregation + residual + bias (+ReLU) ----------------
// Thread f handles features 2f, 2f+1 via half2 gathers.
// out[i][c] = act( mean_{src} GH[src][c] + PR[i][c] + bias[c] )
template <int FH, int FAGG, bool RELU>
__global__ void k_aggfuse(const __half2* __restrict__ GH,
                          const float* __restrict__ PR,
                          const float* __restrict__ bias,
                          float* __restrict__ out, int n) {
    int node = blockIdx.x * blockDim.y + threadIdx.y;
    int f = threadIdx.x;
    if (node >= n) return;
    int o0 = g_off[node];
    int o1 = g_off[node + 1];
    float sx0 = 0.f, sy0 = 0.f, sx1 = 0.f, sy1 = 0.f;
    float sx2 = 0.f, sy2 = 0.f, sx3 = 0.f, sy3 = 0.f;
    int j = o0;
    for (; j + 4 <= o1; j += 4) {
        int a = __ldg(&g_srcs[j]);
        int b = __ldg(&g_srcs[j + 1]);
        int c = __ldg(&g_srcs[j + 2]);
        int d = __ldg(&g_srcs[j + 3]);
        float2 v0 = __half22float2(__ldg(&GH[a * FH + f]));
        float2 v1 = __half22float2(__ldg(&GH[b * FH + f]));
        float2 v2 = __half22float2(__ldg(&GH[c * FH + f]));
        float2 v3 = __half22float2(__ldg(&GH[d * FH + f]));
        sx0 += v0.x; sy0 += v0.y;
        sx1 += v1.x; sy1 += v1.y;
        sx2 += v2.x; sy2 += v2.y;
        sx3 += v3.x; sy3 += v3.y;
    }
    for (; j < o1; j++) {
        int a = __ldg(&g_srcs[j]);
        float2 v = __half22float2(__ldg(&GH[a * FH + f]));
        sx0 += v.x; sy0 += v.y;
    }
    int d = o1 - o0;
    float inv = (d > 0) ? 1.0f / (float)d : 0.0f;
    float mx = ((sx0 + sx1) + (sx2 + sx3)) * inv;
    float my = ((sy0 + sy1) + (sy2 + sy3)) * inv;
    float2 r = *(const float2*)&PR[node * FAGG + 2 * f];
    float2 bb = *(const float2*)&bias[2 * f];
    float vx = mx + r.x + bb.x;
    float vy = my + r.y + bb.y;
    if (RELU) { vx = fmaxf(vx, 0.f); vy = fmaxf(vy, 0.f); }
    *(float2*)&out[node * FAGG + 2 * f] = make_float2(vx, vy);
}

extern "C" void kernel_launch(void* const* d_in, const int* in_sizes, int n_in,
                              void* d_out, int out_size) {
    const float* x   = (const float*)d_in[0];
    const int*   ei  = (const int*)d_in[1];     // int32 edge_index [2, E]
    const float* w1l = (const float*)d_in[2];
    const float* b1  = (const float*)d_in[3];
    const float* w1r = (const float*)d_in[4];
    const float* w2l = (const float*)d_in[5];
    const float* b2  = (const float*)d_in[6];
    const float* w2r = (const float*)d_in[7];
    float* out = (float*)d_out;

    const int N = N_NODES;
    const int E = in_sizes[1] / 2;

    void *p_g1h, *p_p1r, *p_g2h, *p_p2r, *p_h, *p_deg;
    cudaGetSymbolAddress(&p_g1h, g_g1h);
    cudaGetSymbolAddress(&p_p1r, g_p1r);
    cudaGetSymbolAddress(&p_g2h, g_g2h);
    cudaGetSymbolAddress(&p_p2r, g_p2r);
    cudaGetSymbolAddress(&p_h, g_h);
    cudaGetSymbolAddress(&p_deg, g_deg);
    __half2* G1H = (__half2*)p_g1h;
    float*   P1R = (float*)p_p1r;
    __half2* G2H = (__half2*)p_g2h;
    float*   P2R = (float*)p_p2r;
    float*   h   = (float*)p_h;

    // Lazy-create side stream + events (first call is the uncaptured
    // correctness run, so creation happens outside graph capture).
    static cudaStream_t s_side = nullptr;
    static cudaEvent_t ev_fork = nullptr, ev_join = nullptr;
    if (s_side == nullptr) {
        cudaStreamCreateWithFlags(&s_side, cudaStreamNonBlocking);
        cudaEventCreateWithFlags(&ev_fork, cudaEventDisableTiming);
        cudaEventCreateWithFlags(&ev_join, cudaEventDisableTiming);
    }

    // Fork: CSR build on side stream, proj1 concurrently on main stream.
    cudaEventRecord(ev_fork, 0);
    cudaStreamWaitEvent(s_side, ev_fork, 0);

    int e4 = (E + 3) / 4;
    cudaMemsetAsync(p_deg, 0, N * sizeof(int), s_side);
    k_hist<<<(e4 + 255) / 256, 256, 0, s_side>>>(ei, E);
    k_scan<<<1, 1024, 0, s_side>>>(N, E);
    k_scatter<<<(e4 + 255) / 256, 256, 0, s_side>>>(ei, E);
    cudaEventRecord(ev_join, s_side);

    int ggrid = (N + 127) / 128;

    // Layer 1 projection (independent of edges) overlaps CSR build.
    k_proj<192, 6><<<ggrid, 512>>>(x, w1l, w1r, G1H, P1R, N);

    // Join: aggregation needs both CSR and projections.
    cudaStreamWaitEvent(0, ev_join, 0);

    k_aggfuse<48, 96, true><<<(N + 7) / 8, dim3(48, 8)>>>(G1H, P1R, b1, h, N);

    // Layer 2
    k_proj<96, 3><<<ggrid, 512>>>(h, w2l, w2r, G2H, P2R, N);
    k_aggfuse<24, 48, false><<<(N + 15) / 16, dim3(24, 16)>>>(G2H, P2R, b2, out, N);
}